// round 17
// baseline (speedup 1.0000x reference)
#include <cuda_runtime.h>
#include <math.h>

typedef unsigned long long ull;

// ---------------- problem constants ----------------
#define NIMG   1536            // B*S
#define UNITS  48
#define SENS   1283
#define NB     32
#define NS     48
#define H0 48
#define W0 72

// sc0 half: [icpL=8][row 23][pos 0..35][2ic] ; PSTR=72 floats (288B)
#define PSTR 72
#define PLN  (23*PSTR)          // 1656 floats per plane
#define SC0H (8*PLN)            // 13248 floats
#define W1PSZ (16*9*64*2)       // 18432 floats: ull[g=icp*9+j][2*lane+s]
#define W2PSZ (32*9*32*2)       // 18432 floats: [icp32][j9][oc32] ull
#define C1PSZ (11*17*64)        // 11968 floats/img: [y][x17][oc64] FINAL conv1

// ---------------- device scratch ----------------
__device__ float  g_c1[(size_t)NIMG * C1PSZ];       // conv1 final (bias+relu)
__device__ float  g_x [(size_t)NIMG * SENS];
__device__ float  g_sn[(size_t)NIMG * UNITS];
__device__ float  g_sd[(size_t)NIMG * UNITS];
__device__ float4 g_sp[SENS * UNITS];
__device__ float4 g_rp[UNITS * UNITS];
__device__ float  g_skn[UNITS], g_skd[UNITS];
__device__ float  g_nc[UNITS], g_dc[UNITS], g_cmt[UNITS];
__device__ float  g_w1p[W1PSZ];
__device__ ull    g_w2p[W2PSZ / 2];

// ---------------- fast math helpers ----------------
__device__ __forceinline__ float rcpf(float x) {
    float y; asm("rcp.approx.f32 %0, %1;" : "=f"(y) : "f"(x)); return y;
}
__device__ __forceinline__ float tanhf_a(float x) {
    float y; asm("tanh.approx.f32 %0, %1;" : "=f"(y) : "f"(x)); return y;
}
__device__ __forceinline__ ull ffma2(ull a, ull b, ull c) {
    ull d; asm("fma.rn.f32x2 %0, %1, %2, %3;" : "=l"(d) : "l"(a), "l"(b), "l"(c));
    return d;
}
__device__ __forceinline__ float2 unpack2(ull v) {
    float2 r; asm("mov.b64 {%0, %1}, %2;" : "=f"(r.x), "=f"(r.y) : "l"(v));
    return r;
}

// ---------------- prep: sens params + rec params + conv weight repacks ----------
__global__ void k_prep_all(const float* __restrict__ iw, const float* __restrict__ ib,
                           const float* __restrict__ ssig, const float* __restrict__ smu,
                           const float* __restrict__ sw, const float* __restrict__ serev,
                           const int* __restrict__ smask,
                           const float* __restrict__ sigma, const float* __restrict__ mu,
                           const float* __restrict__ wsyn, const float* __restrict__ erev,
                           const int* __restrict__ mask,
                           const float* __restrict__ w1, const float* __restrict__ w2) {
    int idx = blockIdx.x * blockDim.x + threadIdx.x;
    if (idx < SENS * UNITS) {
        int k = idx / UNITS;
        float sg = ssig[idx], m = smu[idx];
        float w  = sw[idx] * (float)smask[idx];
        float A = 0.5f * sg * iw[k];
        float C = 0.5f * sg * (ib[k] - m);
        g_sp[idx] = make_float4(A, C, 0.5f * w * serev[idx], 0.5f * w);
    } else if (idx < SENS * UNITS + UNITS * UNITS) {
        int r = idx - SENS * UNITS;
        float sg = sigma[r], m = mu[r];
        float w  = wsyn[r] * (float)mask[r];
        g_rp[r] = make_float4(0.5f * sg, -0.5f * sg * m, 0.5f * w * erev[r], 0.5f * w);
    } else if (idx < SENS * UNITS + 2304 + 16 * 9 * 64) {
        int u = idx - SENS * UNITS - 2304;         // ull index 0..9215
        int q = u & 63;
        int oc = (q >> 1) + 32 * (q & 1);
        int g = u >> 6, icp = g / 9, j = g % 9;
        g_w1p[u * 2 + 0] = w1[(oc * 32 + 2 * icp) * 9 + j];
        g_w1p[u * 2 + 1] = w1[(oc * 32 + 2 * icp + 1) * 9 + j];
    } else if (idx < SENS * UNITS + 2304 + 16 * 9 * 64 + 32 * 9 * 32) {
        int k = idx - SENS * UNITS - 2304 - 16 * 9 * 64;  // [icp][j][oc] for conv2
        int icp = k / 288, rem = k % 288, j = rem / 32, oc = rem % 32;
        float* dst = (float*)g_w2p;
        dst[k * 2 + 0] = w2[(oc * 64 + 2 * icp) * 9 + j];
        dst[k * 2 + 1] = w2[(oc * 64 + 2 * icp + 1) * 9 + j];
    }
}

__global__ void __launch_bounds__(256) k_prep_const(const float* __restrict__ gleak,
                                                    const float* __restrict__ vleak,
                                                    const float* __restrict__ cm) {
    int u = blockIdx.x, tid = threadIdx.x;
    float kn = 0.f, kd = 0.f;
    for (int k = tid; k < SENS; k += 256) {
        float4 p = g_sp[k * UNITS + u];
        kn += p.z; kd += p.w;
    }
    #pragma unroll
    for (int o = 16; o > 0; o >>= 1) {
        kn += __shfl_xor_sync(0xffffffff, kn, o);
        kd += __shfl_xor_sync(0xffffffff, kd, o);
    }
    __shared__ float swn[8], swd[8];
    if ((tid & 31) == 0) { swn[tid >> 5] = kn; swd[tid >> 5] = kd; }
    __syncthreads();
    if (tid == 0) {
        float tn = 0.f, td = 0.f;
        #pragma unroll
        for (int i = 0; i < 8; i++) { tn += swn[i]; td += swd[i]; }
        g_skn[u] = tn; g_skd[u] = td;
        float rn = 0.f, rd = 0.f;
        for (int p = 0; p < UNITS; p++) { float4 q = g_rp[p * UNITS + u]; rn += q.z; rd += q.w; }
        float cmt = cm[u] * 6.f;
        g_cmt[u] = cmt;
        g_nc[u] = gleak[u] * vleak[u] + rn;
        g_dc[u] = cmt + gleak[u] + rd + 1e-8f;
    }
}

// ---------------- k_cnn: conv0+conv1 full-K, CTA = (xh, img)  [R15-proven 424us] ----
__global__ void __launch_bounds__(352, 2) k_cnn(const float* __restrict__ image,
                                                const float* __restrict__ w0,
                                                const float* __restrict__ b0,
                                                const float* __restrict__ b1) {
    extern __shared__ float sm[];
    float* simg = sm;                // 3456
    float* sw0  = sm + 3456;         // 288
    float* sw1  = sm + 3744;         // 9216 (half of w1p for current kh)
    float* sc0  = sm + 12960;        // 13248  (total 26208 fl = 104832B)
    int xh  = blockIdx.x;            // 0: x 0..8 ; 1: x 9..16
    int img = blockIdx.y;
    int tid = threadIdx.x;

    {   // stage image + conv0 weights (once)
        const float4* isrc = (const float4*)(image + (size_t)img * (H0 * W0));
        float4* d = (float4*)simg;
        for (int i = tid; i < (H0 * W0) / 4; i += 352) d[i] = isrc[i];
        for (int i = tid; i < 288; i += 352) sw0[i] = w0[i];
    }

    int oy = tid >> 5, lane = tid & 31;
    const int NOUT = xh ? 8 : 9;
    ull accA[9], accB[9];
    #pragma unroll
    for (int o = 0; o < 9; o++) { accA[o] = 0ull; accB[o] = 0ull; }

    #pragma unroll 1
    for (int kh = 0; kh < 2; kh++) {
        __syncthreads();
        {   // stage conv1 weight half for this kh (contiguous)
            const float4* ws = (const float4*)g_w1p;
            float4* dw = (float4*)sw1;
            for (int i = tid; i < 2304; i += 352) dw[i] = ws[kh * 2304 + i];
        }
        // ---- conv0: 8 planes (global icp = kh*8 + icpL); warp per (icpL, oy) ----
        {
            for (int task = oy; task < 184; task += 11) {
                int icpL = task / 23, oyc = task % 23;
                int icpG = kh * 8 + icpL;
                float we[9], wo[9];
                #pragma unroll
                for (int j = 0; j < 9; j++) {
                    we[j] = sw0[(2 * icpG) * 9 + j];
                    wo[j] = sw0[(2 * icpG + 1) * 9 + j];
                }
                float be = __ldg(&b0[2 * icpG]), bo = __ldg(&b0[2 * icpG + 1]);
                float2* dst = (float2*)&sc0[icpL * PLN + oyc * PSTR];
                {
                    float ae = be, ao = bo;
                    #pragma unroll
                    for (int ky = 0; ky < 3; ky++) {
                        const float* row = &simg[(2 * oyc + ky) * W0 + 2 * lane];
                        #pragma unroll
                        for (int kx = 0; kx < 3; kx++) {
                            float r = row[kx];
                            ae = fmaf(we[ky * 3 + kx], r, ae);
                            ao = fmaf(wo[ky * 3 + kx], r, ao);
                        }
                    }
                    dst[lane] = make_float2(fmaxf(ae, 0.f), fmaxf(ao, 0.f));
                }
                if (lane < 3) {
                    int ox = 32 + lane;
                    float ae = be, ao = bo;
                    #pragma unroll
                    for (int ky = 0; ky < 3; ky++) {
                        const float* row = &simg[(2 * oyc + ky) * W0 + 2 * ox];
                        #pragma unroll
                        for (int kx = 0; kx < 3; kx++) {
                            float r = row[kx];
                            ae = fmaf(we[ky * 3 + kx], r, ae);
                            ao = fmaf(wo[ky * 3 + kx], r, ao);
                        }
                    }
                    dst[ox] = make_float2(fmaxf(ae, 0.f), fmaxf(ao, 0.f));
                }
            }
        }
        __syncthreads();

        // ---- conv1 accumulate over this kh's 8 planes ----
        const ull* swq = (const ull*)sw1;
        #pragma unroll 1
        for (int icpL = 0; icpL < 8; icpL++) {
            #pragma unroll
            for (int ky = 0; ky < 3; ky++) {
                int r = 2 * oy + ky;
                const ull* rb = ((const ull*)&sc0[icpL * PLN + r * PSTR]) + 18 * xh;
                ulonglong2 wv[3];
                #pragma unroll
                for (int kx = 0; kx < 3; kx++)
                    wv[kx] = *(const ulonglong2*)&swq[(icpL * 9 + ky * 3 + kx) * 64 + 2 * lane];
                {   // chunk 1: outputs 0..4 (pos 0..10 local)
                    ull t[11];
                    const ulonglong2* p2 = (const ulonglong2*)rb;
                    #pragma unroll
                    for (int j = 0; j < 5; j++) { ulonglong2 v = p2[j]; t[2 * j] = v.x; t[2 * j + 1] = v.y; }
                    t[10] = rb[10];
                    #pragma unroll
                    for (int kx = 0; kx < 3; kx++)
                        #pragma unroll
                        for (int o = 0; o < 5; o++) {
                            accA[o] = ffma2(wv[kx].x, t[2 * o + kx], accA[o]);
                            accB[o] = ffma2(wv[kx].y, t[2 * o + kx], accB[o]);
                        }
                }
                {   // chunk 2: outputs 5..NOUT-1 (pos 10..18 local; xh=1 last guarded)
                    ull t[9];
                    const ulonglong2* q2 = (const ulonglong2*)(rb + 10);
                    #pragma unroll
                    for (int j = 0; j < 4; j++) { ulonglong2 v = q2[j]; t[2 * j] = v.x; t[2 * j + 1] = v.y; }
                    t[8] = rb[18 - 18 * xh];   // xh=0: pos 18 ; xh=1: safe dummy
                    #pragma unroll
                    for (int kx = 0; kx < 3; kx++)
                        #pragma unroll
                        for (int o = 5; o < 9; o++)
                            if (o < NOUT) {
                                accA[o] = ffma2(wv[kx].x, t[2 * (o - 5) + kx], accA[o]);
                                accB[o] = ffma2(wv[kx].y, t[2 * (o - 5) + kx], accB[o]);
                            }
                }
            }
        }
    }

    // ---- epilogue: bias + relu, final conv1 -> g_c1 [y][x17][oc64] ----
    float bbA = __ldg(&b1[lane]), bbB = __ldg(&b1[lane + 32]);
    float* base = g_c1 + (size_t)img * C1PSZ + (oy * 17 + xh * 9) * 64;
    #pragma unroll
    for (int o = 0; o < 9; o++)
        if (o < NOUT) {
            float2 ea = unpack2(accA[o]);
            float2 eb = unpack2(accB[o]);
            base[o * 64 + lane]      = fmaxf(ea.x + ea.y + bbA, 0.f);
            base[o * 64 + lane + 32] = fmaxf(eb.x + eb.y + bbB, 0.f);
        }
}

// ---------------- k_conv2 (R9-proven shape): 320 thr, 3 CTAs/SM, __ldg weights ----
__global__ void __launch_bounds__(320, 3) k_conv2(const float* __restrict__ b2,
                                                  const float* __restrict__ relpos) {
    extern __shared__ float sc1[];   // 11968, layout [y][x17][ic64]
    int img = blockIdx.x, tid = threadIdx.x;
    {
        const float4* src = (const float4*)(g_c1 + (size_t)img * C1PSZ);
        float4* d = (float4*)sc1;
        for (int i = tid; i < C1PSZ / 4; i += 320) d[i] = src[i];
    }
    __syncthreads();

    int w   = tid >> 5;          // 0..9
    int oy  = w >> 1;            // 0..4
    int p   = w & 1;             // 0..1
    int oc2 = tid & 31;          // 0..31
    ull acc[4];
    #pragma unroll
    for (int o = 0; o < 4; o++) acc[o] = 0ull;
    #pragma unroll 1
    for (int icp = 0; icp < 32; icp++) {
        #pragma unroll
        for (int ky = 0; ky < 3; ky++) {
            int r = 2 * oy + ky;
            ull t[9];
            #pragma unroll
            for (int j = 0; j < 9; j++)
                t[j] = *(const ull*)&sc1[(r * 17 + 8 * p + j) * 64 + 2 * icp];
            #pragma unroll
            for (int kx = 0; kx < 3; kx++) {
                ull wk = __ldg(&g_w2p[(icp * 9 + ky * 3 + kx) * 32 + oc2]);
                #pragma unroll
                for (int o = 0; o < 4; o++)
                    acc[o] = ffma2(wk, t[2 * o + kx], acc[o]);
            }
        }
    }
    float bb = __ldg(&b2[oc2]);
    float* out = &g_x[(size_t)img * SENS + oc2 * 40 + oy * 8 + 4 * p];
    #pragma unroll
    for (int o = 0; o < 4; o++) {
        float2 e = unpack2(acc[o]);
        out[o] = fmaxf(e.x + e.y + bb, 0.f);
    }
    if (tid < 3) g_x[(size_t)img * SENS + 1280 + tid] = relpos[(size_t)img * 3 + tid];
}

// ---------------- sensory synapse precompute: 12 images/block ----------------
#define SCHUNK 96
#define SIMG   12
__global__ void __launch_bounds__(SIMG * UNITS) k_sens() {
    extern __shared__ float sm3[];
    float4* sp = (float4*)sm3;
    float*  xs = sm3 + SCHUNK * UNITS * 4;
    int tid = threadIdx.x;
    int img0 = blockIdx.x * SIMG;
    for (int i = tid; i < SIMG * SENS; i += SIMG * UNITS)
        xs[i] = g_x[(size_t)img0 * SENS + i];
    int u = tid % UNITS, t = tid / UNITS;
    float accn = 0.f, accd = 0.f;
    const float* xrow = &xs[t * SENS];
    for (int k0 = 0; k0 < SENS; k0 += SCHUNK) {
        int C = min(SCHUNK, SENS - k0);
        __syncthreads();
        for (int i = tid; i < C * UNITS; i += SIMG * UNITS) sp[i] = g_sp[k0 * UNITS + i];
        __syncthreads();
        #pragma unroll 4
        for (int kk = 0; kk < C; kk++) {
            float4 p = sp[kk * UNITS + u];
            float xv = xrow[k0 + kk];
            float tt = tanhf_a(fmaf(xv, p.x, p.y));
            accn = fmaf(p.z, tt, accn);
            accd = fmaf(p.w, tt, accd);
        }
    }
    g_sn[(size_t)(img0 + t) * UNITS + u] = g_skn[u] + accn;
    g_sd[(size_t)(img0 + t) * UNITS + u] = g_skd[u] + accd;
}

// ---------------- LTC recurrence + pooling + head ----------------
__global__ void __launch_bounds__(288) k_ltc(const float* __restrict__ wout,
                                             const float* __restrict__ bout,
                                             const float* __restrict__ whead,
                                             const float* __restrict__ bhead,
                                             float* __restrict__ out) {
    extern __shared__ float sm4[];
    float4* rp   = (float4*)sm4;
    float*  sn   = sm4 + 9216;
    float*  sd   = sn + 2304;
    float*  v    = sd + 2304;
    float*  redn = v + 48;
    float*  redd = redn + 288;
    float*  cmt  = redd + 288;
    float*  nc   = cmt + 48;
    float*  dc   = nc + 48;
    float*  outsum = dc + 48;
    int b = blockIdx.x, tid = threadIdx.x;
    for (int i = tid; i < UNITS * UNITS; i += 288) rp[i] = g_rp[i];
    for (int i = tid; i < NS * UNITS; i += 288) {
        sn[i] = g_sn[(size_t)b * NS * UNITS + i];
        sd[i] = g_sd[(size_t)b * NS * UNITS + i];
    }
    if (tid < UNITS) {
        v[tid] = 0.f;
        cmt[tid] = g_cmt[tid];
        nc[tid]  = g_nc[tid];
        dc[tid]  = g_dc[tid];
    }
    if (tid < 4) outsum[tid] = 0.f;
    __syncthreads();
    int u = tid % UNITS, g = tid / UNITS;
    for (int s = 0; s < NS; s++) {
        for (int it = 0; it < 6; it++) {
            float accn = 0.f, accd = 0.f;
            #pragma unroll
            for (int j = 0; j < 8; j++) {
                int p = g * 8 + j;
                float4 q = rp[p * UNITS + u];
                float tt = tanhf_a(fmaf(v[p], q.x, q.y));
                accn = fmaf(q.z, tt, accn);
                accd = fmaf(q.w, tt, accd);
            }
            redn[g * UNITS + u] = accn;
            redd[g * UNITS + u] = accd;
            __syncthreads();
            if (tid < UNITS) {
                float a = 0.f, d = 0.f;
                #pragma unroll
                for (int gg = 0; gg < 6; gg++) { a += redn[gg * UNITS + tid]; d += redd[gg * UNITS + tid]; }
                float vv  = v[tid];
                float num = fmaf(cmt[tid], vv, nc[tid]) + a + sn[s * UNITS + tid];
                float den = dc[tid] + d + sd[s * UNITS + tid];
                v[tid] = num * rcpf(den);
            }
            __syncthreads();
        }
        if (tid < 4) outsum[tid] += v[tid];
    }
    __syncthreads();
    if (tid == 0) {
        float p[4];
        #pragma unroll
        for (int m = 0; m < 4; m++)
            p[m] = outsum[m] * (1.f / 48.f) * wout[m] + bout[m];
        #pragma unroll
        for (int j = 0; j < 2; j++) {
            float h = bhead[j];
            #pragma unroll
            for (int m = 0; m < 4; m++) h = fmaf(p[m], whead[m * 2 + j], h);
            out[b * 2 + j] = tanhf(h);
        }
    }
}

// ---------------- launch ----------------
extern "C" void kernel_launch(void* const* d_in, const int* in_sizes, int n_in,
                              void* d_out, int out_size) {
    const float* image   = (const float*)d_in[0];
    const float* rel_pos = (const float*)d_in[1];
    const float* w0 = (const float*)d_in[2];
    const float* b0 = (const float*)d_in[3];
    const float* w1 = (const float*)d_in[4];
    const float* b1 = (const float*)d_in[5];
    const float* w2 = (const float*)d_in[6];
    const float* b2 = (const float*)d_in[7];
    const float* input_w = (const float*)d_in[8];
    const float* input_b = (const float*)d_in[9];
    const float* gleak = (const float*)d_in[10];
    const float* vleak = (const float*)d_in[11];
    const float* cm    = (const float*)d_in[12];
    const float* sigma = (const float*)d_in[13];
    const float* mu    = (const float*)d_in[14];
    const float* w_syn = (const float*)d_in[15];
    const float* erev  = (const float*)d_in[16];
    const float* s_sigma = (const float*)d_in[17];
    const float* s_mu    = (const float*)d_in[18];
    const float* s_w     = (const float*)d_in[19];
    const float* s_erev  = (const float*)d_in[20];
    const float* w_out = (const float*)d_in[21];
    const float* b_out = (const float*)d_in[22];
    const float* w_head = (const float*)d_in[23];
    const float* b_head = (const float*)d_in[24];
    const int* syn_mask  = (const int*)d_in[25];
    const int* sens_mask = (const int*)d_in[26];
    float* out = (float*)d_out;

    const int SM_CNN  = (3456 + 288 + 9216 + SC0H) * 4;        // 104832
    const int SM_CV2  = C1PSZ * 4;                             // 47872 (3 CTAs/SM)
    const int SM_SENS = SCHUNK * UNITS * 16 + SIMG * SENS * 4;
    const int SM_LTC  = (9216 + 2304 + 2304 + 48 + 288 + 288 + 48 + 48 + 48 + 4) * 4;
    cudaFuncSetAttribute(k_cnn,   cudaFuncAttributeMaxDynamicSharedMemorySize, SM_CNN);
    cudaFuncSetAttribute(k_conv2, cudaFuncAttributeMaxDynamicSharedMemorySize, SM_CV2);
    cudaFuncSetAttribute(k_sens,  cudaFuncAttributeMaxDynamicSharedMemorySize, SM_SENS);
    cudaFuncSetAttribute(k_ltc,   cudaFuncAttributeMaxDynamicSharedMemorySize, SM_LTC);

    const int NPREP = SENS * UNITS + 2304 + 16 * 9 * 64 + 32 * 9 * 32;
    k_prep_all<<<(NPREP + 255) / 256, 256>>>(input_w, input_b, s_sigma, s_mu,
                                             s_w, s_erev, sens_mask,
                                             sigma, mu, w_syn, erev, syn_mask, w1, w2);
    k_prep_const<<<UNITS, 256>>>(gleak, vleak, cm);
    k_cnn<<<dim3(2, NIMG), 352, SM_CNN>>>(image, w0, b0, b1);
    k_conv2<<<NIMG, 320, SM_CV2>>>(b2, rel_pos);
    k_sens<<<NIMG / SIMG, SIMG * UNITS, SM_SENS>>>();
    k_ltc<<<NB, 288, SM_LTC>>>(w_out, b_out, w_head, b_head, out);
}